// round 1
// baseline (speedup 1.0000x reference)
#include <cuda_runtime.h>
#include <cuda_bf16.h>

// Problem constants (fixed by the dataset)
constexpr int N_SRC   = 100000;
constexpr int N_TGT   = 50000;
constexpr int N_EDGES = 600000;
constexpr int C       = 128;   // in/out channels
constexpr int R       = 7;     // edge types
constexpr int T       = 4;     // node types
constexpr int KREL    = R * C;        // 896
constexpr int KTOT    = KREL + T * C; // 1408

// Scratch (static __device__ arrays: allocation-free per harness rules)
__device__ float g_agg[(size_t)N_TGT * KREL];   // 179.2 MB aggregate buffer [d][r*128+c]
__device__ int   g_cnt[N_TGT * R];              // per (d, r) edge counts
__device__ float g_inv[N_TGT * R];              // 1/max(cnt,1)
__device__ float g_Bt[KTOT * C];                // B transposed: [k][o]

// ---------------------------------------------------------------------------
// Zero the aggregate buffer + counts
// ---------------------------------------------------------------------------
__global__ void zero_kernel() {
    size_t i = (size_t)blockIdx.x * blockDim.x + threadIdx.x;
    const size_t n4 = (size_t)N_TGT * KREL / 4;  // 11.2M float4
    if (i < n4) {
        reinterpret_cast<float4*>(g_agg)[i] = make_float4(0.f, 0.f, 0.f, 0.f);
    }
    if (i < (size_t)N_TGT * R) {
        g_cnt[i] = 0;
    }
}

// ---------------------------------------------------------------------------
// Build transposed weight matrix B[k][o]:
//   k <  896 : rel_w[k/128][o][k%128]
//   k >= 896 : root_w[(k-896)/128][o][k%128]
// ---------------------------------------------------------------------------
__global__ void buildB_kernel(const float* __restrict__ rel_w,
                              const float* __restrict__ root_w) {
    int idx = blockIdx.x * blockDim.x + threadIdx.x;
    if (idx >= KTOT * C) return;
    int k = idx >> 7;
    int o = idx & 127;
    float v;
    if (k < KREL) {
        v = rel_w[(k >> 7) * (C * C) + o * C + (k & 127)];
    } else {
        int kr = k - KREL;
        v = root_w[(kr >> 7) * (C * C) + o * C + (kr & 127)];
    }
    g_Bt[idx] = v;
}

// ---------------------------------------------------------------------------
// Scatter: one warp per edge. Gather x_src row (float4 per lane) and
// atomically add into g_agg[dst][etype*128 + c]; lane 0 bumps the count.
// ---------------------------------------------------------------------------
__global__ void scatter_kernel(const float4* __restrict__ xsrc4,
                               const int* __restrict__ esrc,
                               const int* __restrict__ edst,
                               const int* __restrict__ etype) {
    int gtid = blockIdx.x * blockDim.x + threadIdx.x;
    int e    = gtid >> 5;
    int lane = gtid & 31;
    if (e >= N_EDGES) return;
    int s = esrc[e];
    int d = edst[e];
    int r = etype[e];
    if (lane == 0) atomicAdd(&g_cnt[d * R + r], 1);
    float4 v = xsrc4[(size_t)s * 32 + lane];
    float* base = &g_agg[(size_t)d * KREL + r * C + lane * 4];
    atomicAdd(base + 0, v.x);
    atomicAdd(base + 1, v.y);
    atomicAdd(base + 2, v.z);
    atomicAdd(base + 3, v.w);
}

// ---------------------------------------------------------------------------
// inv = 1/max(cnt, 1)
// ---------------------------------------------------------------------------
__global__ void inv_kernel() {
    int i = blockIdx.x * blockDim.x + threadIdx.x;
    if (i < N_TGT * R) {
        g_inv[i] = 1.0f / fmaxf((float)g_cnt[i], 1.0f);
    }
}

// ---------------------------------------------------------------------------
// Fused GEMM: out[d][o] = sum_k A[d][k] * B[k][o] + root_b[type[d]][o]
//   A[d][k]  (k <  896): g_agg[d][k] * g_inv[d][k/128]   (generated on load)
//   A[d][k]  (k >= 896): (type[d] == (k-896)/128) ? x_target[d][k%128] : 0
// BM=128 rows x BN=128 cols x BK=16, 256 threads, 8x8 per thread.
// ---------------------------------------------------------------------------
__global__ __launch_bounds__(256, 2)
void gemm_kernel(const float* __restrict__ x_target,
                 const float* __restrict__ root_b,
                 const int* __restrict__ ntype,
                 float* __restrict__ out) {
    __shared__ float As[16][128];   // [kk][m]  (transposed on store)
    __shared__ float Bs[16][128];   // [kk][o]

    const int tid = threadIdx.x;
    const int tx  = tid & 15;       // output-col group
    const int ty  = tid >> 4;       // output-row group
    const int row0 = blockIdx.x * 128;

    float acc[8][8];
#pragma unroll
    for (int i = 0; i < 8; i++)
#pragma unroll
        for (int j = 0; j < 8; j++) acc[i][j] = 0.f;

    // A-load mapping: 64 rows per pass, 2 passes; 4 k-elems (one float4) each
    const int arow = tid >> 2;          // 0..63
    const int akv  = (tid & 3) * 4;     // 0,4,8,12

    for (int kb = 0; kb < KTOT; kb += 16) {
        // ---- load A tile (normalized / masked on the fly) ----
#pragma unroll
        for (int h = 0; h < 2; h++) {
            int m = arow + h * 64;
            int d = row0 + m;
            int k = kb + akv;
            float4 v = make_float4(0.f, 0.f, 0.f, 0.f);
            if (d < N_TGT) {
                if (k < KREL) {
                    v = *reinterpret_cast<const float4*>(&g_agg[(size_t)d * KREL + k]);
                    float inv = g_inv[d * R + (k >> 7)];
                    v.x *= inv; v.y *= inv; v.z *= inv; v.w *= inv;
                } else {
                    int kr = k - KREL;
                    int t  = kr >> 7;
                    if (ntype[d] == t) {
                        v = *reinterpret_cast<const float4*>(&x_target[(size_t)d * C + (kr & 127)]);
                    }
                }
            }
            As[akv + 0][m] = v.x;
            As[akv + 1][m] = v.y;
            As[akv + 2][m] = v.z;
            As[akv + 3][m] = v.w;
        }
        // ---- load B tile ----
        {
            int krow = tid >> 4;            // 0..15
            int o4   = (tid & 15) * 4;      // 0..60
#pragma unroll
            for (int h = 0; h < 2; h++) {
                int o = o4 + h * 64;
                *reinterpret_cast<float4*>(&Bs[krow][o]) =
                    *reinterpret_cast<const float4*>(&g_Bt[(size_t)(kb + krow) * C + o]);
            }
        }
        __syncthreads();

        // ---- compute ----
#pragma unroll
        for (int kk = 0; kk < 16; kk++) {
            float a[8], b[8];
            *reinterpret_cast<float4*>(&a[0]) = *reinterpret_cast<float4*>(&As[kk][ty * 8]);
            *reinterpret_cast<float4*>(&a[4]) = *reinterpret_cast<float4*>(&As[kk][ty * 8 + 4]);
            *reinterpret_cast<float4*>(&b[0]) = *reinterpret_cast<float4*>(&Bs[kk][tx * 8]);
            *reinterpret_cast<float4*>(&b[4]) = *reinterpret_cast<float4*>(&Bs[kk][tx * 8 + 4]);
#pragma unroll
            for (int i = 0; i < 8; i++)
#pragma unroll
                for (int j = 0; j < 8; j++) acc[i][j] += a[i] * b[j];
        }
        __syncthreads();
    }

    // ---- epilogue: add root bias, store ----
#pragma unroll
    for (int i = 0; i < 8; i++) {
        int d = row0 + ty * 8 + i;
        if (d >= N_TGT) continue;
        int t = ntype[d];
        const float* bias = &root_b[t * C];
        float* orow = &out[(size_t)d * C];
#pragma unroll
        for (int j = 0; j < 8; j += 4) {
            int n = tx * 8 + j;
            float4 w;
            w.x = acc[i][j + 0] + bias[n + 0];
            w.y = acc[i][j + 1] + bias[n + 1];
            w.z = acc[i][j + 2] + bias[n + 2];
            w.w = acc[i][j + 3] + bias[n + 3];
            *reinterpret_cast<float4*>(&orow[n]) = w;
        }
    }
}

// ---------------------------------------------------------------------------
extern "C" void kernel_launch(void* const* d_in, const int* in_sizes, int n_in,
                              void* d_out, int out_size) {
    const float* x_src     = (const float*)d_in[0];
    const float* x_target  = (const float*)d_in[1];
    const float* rel_w     = (const float*)d_in[2];
    const float* root_w    = (const float*)d_in[3];
    const float* root_b    = (const float*)d_in[4];
    const int*   edge_src  = (const int*)d_in[5];
    const int*   edge_dst  = (const int*)d_in[6];
    const int*   edge_type = (const int*)d_in[7];
    const int*   ntype     = (const int*)d_in[8];
    float*       out       = (float*)d_out;

    (void)in_sizes; (void)n_in; (void)out_size;

    const int n_zero4 = (int)((size_t)N_TGT * KREL / 4);             // 11.2M
    zero_kernel<<<(n_zero4 + 255) / 256, 256>>>();
    buildB_kernel<<<(KTOT * C + 255) / 256, 256>>>(rel_w, root_w);
    scatter_kernel<<<(N_EDGES * 32 + 255) / 256, 256>>>(
        (const float4*)x_src, edge_src, edge_dst, edge_type);
    inv_kernel<<<(N_TGT * R + 255) / 256, 256>>>();
    gemm_kernel<<<(N_TGT + 127) / 128, 256>>>(x_target, root_b, ntype, out);
}

// round 7
// speedup vs baseline: 1.7731x; 1.7731x over previous
#include <cuda_runtime.h>
#include <cuda_bf16.h>
#include <cstdint>

// Problem constants (fixed by the dataset)
constexpr int N_SRC   = 100000;
constexpr int N_TGT   = 50000;
constexpr int N_EDGES = 600000;
constexpr int C       = 128;   // in/out channels
constexpr int R       = 7;     // edge types
constexpr int T       = 4;     // node types
constexpr int KREL    = R * C;        // 896
constexpr int KTOT    = KREL + T * C; // 1408

// Scratch (static __device__ arrays: allocation-free per harness rules)
__device__ float g_agg[(size_t)N_TGT * KREL];   // 179.2 MB aggregate [d][r*128+c]
__device__ int   g_cnt[N_TGT * R];
__device__ float g_inv[N_TGT * R];
__device__ __nv_bfloat16 g_Bhi[(size_t)C * KTOT];  // [o][k] bf16 hi
__device__ __nv_bfloat16 g_Blo[(size_t)C * KTOT];  // [o][k] bf16 lo (residual)

// ---------------------------------------------------------------------------
__global__ void zero_kernel() {
    size_t i = (size_t)blockIdx.x * blockDim.x + threadIdx.x;
    const size_t n4 = (size_t)N_TGT * KREL / 4;
    if (i < n4) reinterpret_cast<float4*>(g_agg)[i] = make_float4(0.f, 0.f, 0.f, 0.f);
    if (i < (size_t)N_TGT * R) g_cnt[i] = 0;
}

// ---------------------------------------------------------------------------
// Build B[o][k] split into bf16 hi + lo.
//   k <  896 : rel_w[k/128][o][k%128]
//   k >= 896 : root_w[(k-896)/128][o][k%128]
// ---------------------------------------------------------------------------
__global__ void buildB_kernel(const float* __restrict__ rel_w,
                              const float* __restrict__ root_w) {
    int idx = blockIdx.x * blockDim.x + threadIdx.x;
    if (idx >= C * KTOT) return;
    int o = idx / KTOT;
    int k = idx - o * KTOT;
    float w;
    if (k < KREL) {
        w = rel_w[(k >> 7) * (C * C) + o * C + (k & 127)];
    } else {
        int kr = k - KREL;
        w = root_w[(kr >> 7) * (C * C) + o * C + (kr & 127)];
    }
    __nv_bfloat16 hi = __float2bfloat16(w);
    __nv_bfloat16 lo = __float2bfloat16(w - __bfloat162float(hi));
    g_Bhi[idx] = hi;
    g_Blo[idx] = lo;
}

// ---------------------------------------------------------------------------
// Scatter: one warp per edge; one red.v4.f32 (16B) per lane, lane0 counts.
// ---------------------------------------------------------------------------
__global__ void scatter_kernel(const float4* __restrict__ xsrc4,
                               const int* __restrict__ esrc,
                               const int* __restrict__ edst,
                               const int* __restrict__ etype) {
    int gtid = blockIdx.x * blockDim.x + threadIdx.x;
    int e    = gtid >> 5;
    int lane = gtid & 31;
    if (e >= N_EDGES) return;
    int s = esrc[e];
    int d = edst[e];
    int r = etype[e];
    if (lane == 0) atomicAdd(&g_cnt[d * R + r], 1);
    float4 v = xsrc4[(size_t)s * 32 + lane];
    float* base = &g_agg[(size_t)d * KREL + r * C + lane * 4];
    asm volatile("red.global.add.v4.f32 [%0], {%1,%2,%3,%4};"
                 :: "l"(base), "f"(v.x), "f"(v.y), "f"(v.z), "f"(v.w)
                 : "memory");
}

// ---------------------------------------------------------------------------
__global__ void inv_kernel() {
    int i = blockIdx.x * blockDim.x + threadIdx.x;
    if (i < N_TGT * R) g_inv[i] = 1.0f / fmaxf((float)g_cnt[i], 1.0f);
}

// ---------------------------------------------------------------------------
// Tensor-core GEMM (mma.sync m16n8k16 bf16, hi/lo 3-pass split, fp32 accum).
// Manual fragment loads per the PTX fragment spec:
//   A frag: a0=(g,t2) a1=(g+8,t2) a2=(g,t2+8) a3=(g+8,t2+8)  [row g=lane>>2, t2=(lane&3)*2]
//   B frag: b0=(k=t2,n=g) b1=(k=t2+8,n=g)
//   C frag: c0,c1=(g, t2+{0,1}); c2,c3=(g+8, same)
// Block 128x128, BK=32, 256 threads / 8 warps (warp tile 32x64).
// ---------------------------------------------------------------------------
__device__ __forceinline__ void mma_bf16(float& d0, float& d1, float& d2, float& d3,
                                         uint32_t a0, uint32_t a1, uint32_t a2, uint32_t a3,
                                         uint32_t b0, uint32_t b1) {
    asm volatile(
        "mma.sync.aligned.m16n8k16.row.col.f32.bf16.bf16.f32 "
        "{%0,%1,%2,%3}, {%4,%5,%6,%7}, {%8,%9}, {%0,%1,%2,%3};"
        : "+f"(d0), "+f"(d1), "+f"(d2), "+f"(d3)
        : "r"(a0), "r"(a1), "r"(a2), "r"(a3), "r"(b0), "r"(b1));
}

constexpr int SPAD = 40;  // bf16 elems per smem row (32 data + 8 pad) = 20 words

__global__ __launch_bounds__(256, 1)
void gemm_kernel(const float* __restrict__ x_target,
                 const float* __restrict__ root_b,
                 const int* __restrict__ ntype,
                 float* __restrict__ out) {
    __shared__ __nv_bfloat16 As_hi[128][SPAD];
    __shared__ __nv_bfloat16 As_lo[128][SPAD];
    __shared__ __nv_bfloat16 Bs_hi[128][SPAD];
    __shared__ __nv_bfloat16 Bs_lo[128][SPAD];

    const int tid  = threadIdx.x;
    const int lane = tid & 31;
    const int wid  = tid >> 5;
    const int wm   = (wid & 3) * 32;   // warp row offset
    const int wn   = (wid >> 2) * 64;  // warp col offset
    const int row0 = blockIdx.x * 128;
    const int g    = lane >> 2;        // fragment row/col group
    const int t2   = (lane & 3) * 2;   // fragment k pair

    float acc[2][8][4];
#pragma unroll
    for (int i = 0; i < 2; i++)
#pragma unroll
        for (int j = 0; j < 8; j++)
#pragma unroll
            for (int q = 0; q < 4; q++) acc[i][j][q] = 0.f;

    // Tile-loader mapping: thread -> (row = tid>>1, 16 consecutive k)
    const int lrow = tid >> 1;
    const int lkof = (tid & 1) * 16;

    for (int kb = 0; kb < KTOT; kb += 32) {
        // ---- build A tile (fp32 -> hi/lo bf16, normalized / type-masked) ----
        {
            int d = row0 + lrow;
            float scale = 0.f;
            const float* src = nullptr;
            if (d < N_TGT) {
                if (kb < KREL) {
                    scale = g_inv[d * R + (kb >> 7)];
                    src = &g_agg[(size_t)d * KREL + kb + lkof];
                } else {
                    int kr = kb - KREL;
                    if (ntype[d] == (kr >> 7)) {
                        scale = 1.f;
                        src = &x_target[(size_t)d * C + (kr & 127) + lkof];
                    }
                }
            }
#pragma unroll
            for (int i = 0; i < 4; i++) {
                float4 v = src ? *reinterpret_cast<const float4*>(src + i * 4)
                               : make_float4(0.f, 0.f, 0.f, 0.f);
                v.x *= scale; v.y *= scale; v.z *= scale; v.w *= scale;
                __nv_bfloat16 hx = __float2bfloat16(v.x);
                __nv_bfloat16 hy = __float2bfloat16(v.y);
                __nv_bfloat16 hz = __float2bfloat16(v.z);
                __nv_bfloat16 hw = __float2bfloat16(v.w);
                __nv_bfloat16 lx = __float2bfloat16(v.x - __bfloat162float(hx));
                __nv_bfloat16 ly = __float2bfloat16(v.y - __bfloat162float(hy));
                __nv_bfloat16 lz = __float2bfloat16(v.z - __bfloat162float(hz));
                __nv_bfloat16 lw = __float2bfloat16(v.w - __bfloat162float(hw));
                int kc = lkof + i * 4;
                *reinterpret_cast<__nv_bfloat162*>(&As_hi[lrow][kc])     = __nv_bfloat162(hx, hy);
                *reinterpret_cast<__nv_bfloat162*>(&As_hi[lrow][kc + 2]) = __nv_bfloat162(hz, hw);
                *reinterpret_cast<__nv_bfloat162*>(&As_lo[lrow][kc])     = __nv_bfloat162(lx, ly);
                *reinterpret_cast<__nv_bfloat162*>(&As_lo[lrow][kc + 2]) = __nv_bfloat162(lz, lw);
            }
        }
        // ---- load B tiles: 16 bf16 per thread = TWO uint4 (16B) loads each ----
        // (round-2/3 bug: a single uint4 is only 8 bf16 -> half the tile was
        //  uninitialized smem -> NaN. Fixed here.)
        {
            const size_t gof = (size_t)lrow * KTOT + kb + lkof;
            *reinterpret_cast<uint4*>(&Bs_hi[lrow][lkof]) =
                *reinterpret_cast<const uint4*>(&g_Bhi[gof]);
            *reinterpret_cast<uint4*>(&Bs_hi[lrow][lkof + 8]) =
                *reinterpret_cast<const uint4*>(&g_Bhi[gof + 8]);
            *reinterpret_cast<uint4*>(&Bs_lo[lrow][lkof]) =
                *reinterpret_cast<const uint4*>(&g_Blo[gof]);
            *reinterpret_cast<uint4*>(&Bs_lo[lrow][lkof + 8]) =
                *reinterpret_cast<const uint4*>(&g_Blo[gof + 8]);
        }
        __syncthreads();

        // ---- compute: 2 k16 steps, 3 split passes, manual fragment loads ----
#pragma unroll
        for (int ks = 0; ks < 2; ks++) {
            const int k0 = ks * 16;
            uint32_t ah[2][4], al[2][4];
#pragma unroll
            for (int mt = 0; mt < 2; mt++) {
                int r = wm + mt * 16 + g;
                ah[mt][0] = *reinterpret_cast<const uint32_t*>(&As_hi[r][k0 + t2]);
                ah[mt][1] = *reinterpret_cast<const uint32_t*>(&As_hi[r + 8][k0 + t2]);
                ah[mt][2] = *reinterpret_cast<const uint32_t*>(&As_hi[r][k0 + t2 + 8]);
                ah[mt][3] = *reinterpret_cast<const uint32_t*>(&As_hi[r + 8][k0 + t2 + 8]);
                al[mt][0] = *reinterpret_cast<const uint32_t*>(&As_lo[r][k0 + t2]);
                al[mt][1] = *reinterpret_cast<const uint32_t*>(&As_lo[r + 8][k0 + t2]);
                al[mt][2] = *reinterpret_cast<const uint32_t*>(&As_lo[r][k0 + t2 + 8]);
                al[mt][3] = *reinterpret_cast<const uint32_t*>(&As_lo[r + 8][k0 + t2 + 8]);
            }
            uint32_t bh[8][2], bl[8][2];
#pragma unroll
            for (int nt = 0; nt < 8; nt++) {
                int n = wn + nt * 8 + g;
                bh[nt][0] = *reinterpret_cast<const uint32_t*>(&Bs_hi[n][k0 + t2]);
                bh[nt][1] = *reinterpret_cast<const uint32_t*>(&Bs_hi[n][k0 + t2 + 8]);
                bl[nt][0] = *reinterpret_cast<const uint32_t*>(&Bs_lo[n][k0 + t2]);
                bl[nt][1] = *reinterpret_cast<const uint32_t*>(&Bs_lo[n][k0 + t2 + 8]);
            }
#pragma unroll
            for (int mt = 0; mt < 2; mt++)
#pragma unroll
                for (int nt = 0; nt < 8; nt++) {
                    mma_bf16(acc[mt][nt][0], acc[mt][nt][1], acc[mt][nt][2], acc[mt][nt][3],
                             ah[mt][0], ah[mt][1], ah[mt][2], ah[mt][3],
                             bh[nt][0], bh[nt][1]);
                    mma_bf16(acc[mt][nt][0], acc[mt][nt][1], acc[mt][nt][2], acc[mt][nt][3],
                             ah[mt][0], ah[mt][1], ah[mt][2], ah[mt][3],
                             bl[nt][0], bl[nt][1]);
                    mma_bf16(acc[mt][nt][0], acc[mt][nt][1], acc[mt][nt][2], acc[mt][nt][3],
                             al[mt][0], al[mt][1], al[mt][2], al[mt][3],
                             bh[nt][0], bh[nt][1]);
                }
        }
        __syncthreads();
    }

    // ---- epilogue: add root bias, store float2 per fragment half ----
#pragma unroll
    for (int mt = 0; mt < 2; mt++) {
#pragma unroll
        for (int half = 0; half < 2; half++) {
            int d = row0 + wm + mt * 16 + g + half * 8;
            if (d >= N_TGT) continue;
            int t = ntype[d];
            const float* bias = &root_b[t * C];
            float* orow = &out[(size_t)d * C];
#pragma unroll
            for (int nt = 0; nt < 8; nt++) {
                int col = wn + nt * 8 + t2;
                float2 w;
                w.x = acc[mt][nt][2 * half + 0] + bias[col + 0];
                w.y = acc[mt][nt][2 * half + 1] + bias[col + 1];
                *reinterpret_cast<float2*>(&orow[col]) = w;
            }
        }
    }
}

// ---------------------------------------------------------------------------
extern "C" void kernel_launch(void* const* d_in, const int* in_sizes, int n_in,
                              void* d_out, int out_size) {
    const float* x_src     = (const float*)d_in[0];
    const float* x_target  = (const float*)d_in[1];
    const float* rel_w     = (const float*)d_in[2];
    const float* root_w    = (const float*)d_in[3];
    const float* root_b    = (const float*)d_in[4];
    const int*   edge_src  = (const int*)d_in[5];
    const int*   edge_dst  = (const int*)d_in[6];
    const int*   edge_type = (const int*)d_in[7];
    const int*   ntype     = (const int*)d_in[8];
    float*       out       = (float*)d_out;

    (void)in_sizes; (void)n_in; (void)out_size;

    const int n_zero4 = (int)((size_t)N_TGT * KREL / 4);
    zero_kernel<<<(n_zero4 + 255) / 256, 256>>>();
    buildB_kernel<<<(C * KTOT + 255) / 256, 256>>>(rel_w, root_w);
    scatter_kernel<<<(N_EDGES * 32 + 255) / 256, 256>>>(
        (const float4*)x_src, edge_src, edge_dst, edge_type);
    inv_kernel<<<(N_TGT * R + 255) / 256, 256>>>();
    gemm_kernel<<<(N_TGT + 127) / 128, 256>>>(x_target, root_b, ntype, out);
}

// round 8
// speedup vs baseline: 2.2917x; 1.2925x over previous
#include <cuda_runtime.h>
#include <cuda_bf16.h>
#include <cstdint>

// Problem constants (fixed by the dataset)
constexpr int N_SRC   = 100000;
constexpr int N_TGT   = 50000;
constexpr int N_EDGES = 600000;
constexpr int C       = 128;   // in/out channels
constexpr int R       = 7;     // edge types
constexpr int T       = 4;     // node types
constexpr int KREL    = R * C;        // 896
constexpr int KTOT    = KREL + T * C; // 1408

// Scratch (static __device__ arrays: allocation-free per harness rules)
__device__ float g_agg[(size_t)N_TGT * KREL];   // 179.2 MB aggregate [d][r*128+c]
__device__ int   g_cnt[N_TGT * R];
__device__ float g_inv[N_TGT * R];
__device__ __nv_bfloat16 g_Bhi[(size_t)C * KTOT];  // [o][k] bf16 hi
__device__ __nv_bfloat16 g_Blo[(size_t)C * KTOT];  // [o][k] bf16 lo (residual)

// ---------------------------------------------------------------------------
__global__ void zero_kernel() {
    size_t i = (size_t)blockIdx.x * blockDim.x + threadIdx.x;
    const size_t n4 = (size_t)N_TGT * KREL / 4;
    if (i < n4) reinterpret_cast<float4*>(g_agg)[i] = make_float4(0.f, 0.f, 0.f, 0.f);
    if (i < (size_t)N_TGT * R) g_cnt[i] = 0;
}

// ---------------------------------------------------------------------------
// Build B[o][k] split into bf16 hi + lo.
// ---------------------------------------------------------------------------
__global__ void buildB_kernel(const float* __restrict__ rel_w,
                              const float* __restrict__ root_w) {
    int idx = blockIdx.x * blockDim.x + threadIdx.x;
    if (idx >= C * KTOT) return;
    int o = idx / KTOT;
    int k = idx - o * KTOT;
    float w;
    if (k < KREL) {
        w = rel_w[(k >> 7) * (C * C) + o * C + (k & 127)];
    } else {
        int kr = k - KREL;
        w = root_w[(kr >> 7) * (C * C) + o * C + (kr & 127)];
    }
    __nv_bfloat16 hi = __float2bfloat16(w);
    __nv_bfloat16 lo = __float2bfloat16(w - __bfloat162float(hi));
    g_Bhi[idx] = hi;
    g_Blo[idx] = lo;
}

// ---------------------------------------------------------------------------
// Scatter: one warp per edge; one red.v4.f32 (16B) per lane, lane0 counts.
// ---------------------------------------------------------------------------
__global__ void scatter_kernel(const float4* __restrict__ xsrc4,
                               const int* __restrict__ esrc,
                               const int* __restrict__ edst,
                               const int* __restrict__ etype) {
    int gtid = blockIdx.x * blockDim.x + threadIdx.x;
    int e    = gtid >> 5;
    int lane = gtid & 31;
    if (e >= N_EDGES) return;
    int s = esrc[e];
    int d = edst[e];
    int r = etype[e];
    if (lane == 0) atomicAdd(&g_cnt[d * R + r], 1);
    float4 v = xsrc4[(size_t)s * 32 + lane];
    float* base = &g_agg[(size_t)d * KREL + r * C + lane * 4];
    asm volatile("red.global.add.v4.f32 [%0], {%1,%2,%3,%4};"
                 :: "l"(base), "f"(v.x), "f"(v.y), "f"(v.z), "f"(v.w)
                 : "memory");
}

// ---------------------------------------------------------------------------
__global__ void inv_kernel() {
    int i = blockIdx.x * blockDim.x + threadIdx.x;
    if (i < N_TGT * R) g_inv[i] = 1.0f / fmaxf((float)g_cnt[i], 1.0f);
}

// ---------------------------------------------------------------------------
// Tensor-core GEMM, register-prefetch pipelined, ldmatrix fragment loads.
// Block 128x128, BK=32, 256 threads / 8 warps (warp tile 32x64).
// ---------------------------------------------------------------------------
__device__ __forceinline__ uint32_t smem_u32(const void* p) {
    return (uint32_t)__cvta_generic_to_shared(p);
}
__device__ __forceinline__ void ldsm_x4(uint32_t& r0, uint32_t& r1,
                                        uint32_t& r2, uint32_t& r3, uint32_t addr) {
    asm volatile("ldmatrix.sync.aligned.m8n8.x4.shared.b16 {%0,%1,%2,%3}, [%4];"
                 : "=r"(r0), "=r"(r1), "=r"(r2), "=r"(r3) : "r"(addr));
}
__device__ __forceinline__ void mma_bf16(float& d0, float& d1, float& d2, float& d3,
                                         uint32_t a0, uint32_t a1, uint32_t a2, uint32_t a3,
                                         uint32_t b0, uint32_t b1) {
    asm volatile(
        "mma.sync.aligned.m16n8k16.row.col.f32.bf16.bf16.f32 "
        "{%0,%1,%2,%3}, {%4,%5,%6,%7}, {%8,%9}, {%0,%1,%2,%3};"
        : "+f"(d0), "+f"(d1), "+f"(d2), "+f"(d3)
        : "r"(a0), "r"(a1), "r"(a2), "r"(a3), "r"(b0), "r"(b1));
}

constexpr int SPAD = 40;  // bf16 elems per smem row (32 data + 8 pad) = 20 words

__global__ __launch_bounds__(256, 1)
void gemm_kernel(const float* __restrict__ x_target,
                 const float* __restrict__ root_b,
                 const int* __restrict__ ntype,
                 float* __restrict__ out) {
    __shared__ __nv_bfloat16 As_hi[128][SPAD];
    __shared__ __nv_bfloat16 As_lo[128][SPAD];
    __shared__ __nv_bfloat16 Bs_hi[128][SPAD];
    __shared__ __nv_bfloat16 Bs_lo[128][SPAD];

    const int tid  = threadIdx.x;
    const int lane = tid & 31;
    const int wid  = tid >> 5;
    const int wm   = (wid & 3) * 32;   // warp row offset
    const int wn   = (wid >> 2) * 64;  // warp col offset
    const int row0 = blockIdx.x * 128;
    const int g    = lane >> 2;        // fragment row/col group
    const int t2   = (lane & 3) * 2;   // fragment k pair

    // ldmatrix quadrant addressing (lane -> row within a 16x16 / 16(n)x16(k) tile)
    const int lq  = lane >> 3;   // quadrant 0..3
    const int lr8 = lane & 7;    // row within 8
    // A: quadrants (row+0,k0) (row+8,k0) (row+0,k+8) (row+8,k+8)
    const int a_ro = ((lq & 1) ? 8 : 0) + lr8;
    const int a_co = (lq & 2) ? 8 : 0;
    // B: quadrants (n+0,k0) (n+0,k+8) (n+8,k0) (n+8,k+8)
    const int b_ro = ((lq & 2) ? 8 : 0) + lr8;
    const int b_co = (lq & 1) ? 8 : 0;

    float acc[2][8][4];
#pragma unroll
    for (int i = 0; i < 2; i++)
#pragma unroll
        for (int j = 0; j < 8; j++)
#pragma unroll
            for (int q = 0; q < 4; q++) acc[i][j][q] = 0.f;

    // Tile-loader mapping: thread -> (row = tid>>1, 16 consecutive k)
    const int lrow = tid >> 1;
    const int lkof = (tid & 1) * 16;
    const int dmy  = row0 + lrow;                         // my A row
    const int myt  = (dmy < N_TGT) ? ntype[dmy] : -1;     // hoisted node type

    // ---- prefetch registers ----
    float4 pa[4];
    float  pscale;
    uint4  pbh0, pbh1, pbl0, pbl1;

#define PREFETCH(KB_)                                                          \
    do {                                                                       \
        const int kb_ = (KB_);                                                 \
        const float* src = nullptr;                                            \
        pscale = 0.f;                                                          \
        if (dmy < N_TGT) {                                                     \
            if (kb_ < KREL) {                                                  \
                pscale = g_inv[dmy * R + (kb_ >> 7)];                          \
                src = &g_agg[(size_t)dmy * KREL + kb_ + lkof];                 \
            } else {                                                           \
                int kr_ = kb_ - KREL;                                          \
                if (myt == (kr_ >> 7)) {                                       \
                    pscale = 1.f;                                              \
                    src = &x_target[(size_t)dmy * C + (kr_ & 127) + lkof];     \
                }                                                              \
            }                                                                  \
        }                                                                      \
        if (src) {                                                             \
            pa[0] = *reinterpret_cast<const float4*>(src);                     \
            pa[1] = *reinterpret_cast<const float4*>(src + 4);                 \
            pa[2] = *reinterpret_cast<const float4*>(src + 8);                 \
            pa[3] = *reinterpret_cast<const float4*>(src + 12);                \
        } else {                                                               \
            pa[0] = pa[1] = pa[2] = pa[3] = make_float4(0.f, 0.f, 0.f, 0.f);   \
        }                                                                      \
        const size_t gof_ = (size_t)lrow * KTOT + kb_ + lkof;                  \
        pbh0 = *reinterpret_cast<const uint4*>(&g_Bhi[gof_]);                  \
        pbh1 = *reinterpret_cast<const uint4*>(&g_Bhi[gof_ + 8]);              \
        pbl0 = *reinterpret_cast<const uint4*>(&g_Blo[gof_]);                  \
        pbl1 = *reinterpret_cast<const uint4*>(&g_Blo[gof_ + 8]);              \
    } while (0)

    PREFETCH(0);

    for (int kb = 0; kb < KTOT; kb += 32) {
        // ---- publish prefetched tile to smem ----
#pragma unroll
        for (int i = 0; i < 4; i++) {
            float4 v = pa[i];
            v.x *= pscale; v.y *= pscale; v.z *= pscale; v.w *= pscale;
            __nv_bfloat16 hx = __float2bfloat16(v.x);
            __nv_bfloat16 hy = __float2bfloat16(v.y);
            __nv_bfloat16 hz = __float2bfloat16(v.z);
            __nv_bfloat16 hw = __float2bfloat16(v.w);
            __nv_bfloat16 lx = __float2bfloat16(v.x - __bfloat162float(hx));
            __nv_bfloat16 ly = __float2bfloat16(v.y - __bfloat162float(hy));
            __nv_bfloat16 lz = __float2bfloat16(v.z - __bfloat162float(hz));
            __nv_bfloat16 lw = __float2bfloat16(v.w - __bfloat162float(hw));
            int kc = lkof + i * 4;
            *reinterpret_cast<__nv_bfloat162*>(&As_hi[lrow][kc])     = __nv_bfloat162(hx, hy);
            *reinterpret_cast<__nv_bfloat162*>(&As_hi[lrow][kc + 2]) = __nv_bfloat162(hz, hw);
            *reinterpret_cast<__nv_bfloat162*>(&As_lo[lrow][kc])     = __nv_bfloat162(lx, ly);
            *reinterpret_cast<__nv_bfloat162*>(&As_lo[lrow][kc + 2]) = __nv_bfloat162(lz, lw);
        }
        *reinterpret_cast<uint4*>(&Bs_hi[lrow][lkof])     = pbh0;
        *reinterpret_cast<uint4*>(&Bs_hi[lrow][lkof + 8]) = pbh1;
        *reinterpret_cast<uint4*>(&Bs_lo[lrow][lkof])     = pbl0;
        *reinterpret_cast<uint4*>(&Bs_lo[lrow][lkof + 8]) = pbl1;
        __syncthreads();

        // ---- prefetch next iteration (latency hidden behind compute) ----
        if (kb + 32 < KTOT) PREFETCH(kb + 32);

        // ---- compute: 2 k16 steps, 3 split passes, ldmatrix loads ----
#pragma unroll
        for (int ks = 0; ks < 2; ks++) {
            const int k0 = ks * 16;
            uint32_t ah[2][4], al[2][4];
#pragma unroll
            for (int mt = 0; mt < 2; mt++) {
                int r = wm + mt * 16 + a_ro;
                ldsm_x4(ah[mt][0], ah[mt][1], ah[mt][2], ah[mt][3],
                        smem_u32(&As_hi[r][k0 + a_co]));
                ldsm_x4(al[mt][0], al[mt][1], al[mt][2], al[mt][3],
                        smem_u32(&As_lo[r][k0 + a_co]));
            }
            uint32_t bh[8][2], bl[8][2];
#pragma unroll
            for (int p = 0; p < 4; p++) {
                int n = wn + p * 16 + b_ro;
                uint32_t r0, r1, r2, r3;
                ldsm_x4(r0, r1, r2, r3, smem_u32(&Bs_hi[n][k0 + b_co]));
                bh[2 * p][0] = r0; bh[2 * p][1] = r1;
                bh[2 * p + 1][0] = r2; bh[2 * p + 1][1] = r3;
                ldsm_x4(r0, r1, r2, r3, smem_u32(&Bs_lo[n][k0 + b_co]));
                bl[2 * p][0] = r0; bl[2 * p][1] = r1;
                bl[2 * p + 1][0] = r2; bl[2 * p + 1][1] = r3;
            }
#pragma unroll
            for (int mt = 0; mt < 2; mt++)
#pragma unroll
                for (int nt = 0; nt < 8; nt++) {
                    mma_bf16(acc[mt][nt][0], acc[mt][nt][1], acc[mt][nt][2], acc[mt][nt][3],
                             ah[mt][0], ah[mt][1], ah[mt][2], ah[mt][3],
                             bh[nt][0], bh[nt][1]);
                    mma_bf16(acc[mt][nt][0], acc[mt][nt][1], acc[mt][nt][2], acc[mt][nt][3],
                             ah[mt][0], ah[mt][1], ah[mt][2], ah[mt][3],
                             bl[nt][0], bl[nt][1]);
                    mma_bf16(acc[mt][nt][0], acc[mt][nt][1], acc[mt][nt][2], acc[mt][nt][3],
                             al[mt][0], al[mt][1], al[mt][2], al[mt][3],
                             bh[nt][0], bh[nt][1]);
                }
        }
        __syncthreads();
    }
#undef PREFETCH

    // ---- epilogue: add root bias, store float2 per fragment half ----
#pragma unroll
    for (int mt = 0; mt < 2; mt++) {
#pragma unroll
        for (int half = 0; half < 2; half++) {
            int d = row0 + wm + mt * 16 + g + half * 8;
            if (d >= N_TGT) continue;
            int t = ntype[d];
            const float* bias = &root_b[t * C];
            float* orow = &out[(size_t)d * C];
#pragma unroll
            for (int nt = 0; nt < 8; nt++) {
                int col = wn + nt * 8 + t2;
                float2 w;
                w.x = acc[mt][nt][2 * half + 0] + bias[col + 0];
                w.y = acc[mt][nt][2 * half + 1] + bias[col + 1];
                *reinterpret_cast<float2*>(&orow[col]) = w;
            }
        }
    }
}

// ---------------------------------------------------------------------------
extern "C" void kernel_launch(void* const* d_in, const int* in_sizes, int n_in,
                              void* d_out, int out_size) {
    const float* x_src     = (const float*)d_in[0];
    const float* x_target  = (const float*)d_in[1];
    const float* rel_w     = (const float*)d_in[2];
    const float* root_w    = (const float*)d_in[3];
    const float* root_b    = (const float*)d_in[4];
    const int*   edge_src  = (const int*)d_in[5];
    const int*   edge_dst  = (const int*)d_in[6];
    const int*   edge_type = (const int*)d_in[7];
    const int*   ntype     = (const int*)d_in[8];
    float*       out       = (float*)d_out;

    (void)in_sizes; (void)n_in; (void)out_size;

    const int n_zero4 = (int)((size_t)N_TGT * KREL / 4);
    zero_kernel<<<(n_zero4 + 255) / 256, 256>>>();
    buildB_kernel<<<(C * KTOT + 255) / 256, 256>>>(rel_w, root_w);
    scatter_kernel<<<(N_EDGES * 32 + 255) / 256, 256>>>(
        (const float4*)x_src, edge_src, edge_dst, edge_type);
    inv_kernel<<<(N_TGT * R + 255) / 256, 256>>>();
    gemm_kernel<<<(N_TGT + 127) / 128, 256>>>(x_target, root_b, ntype, out);
}